// round 3
// baseline (speedup 1.0000x reference)
#include <cuda_runtime.h>
#include <cuda_bf16.h>
#include <stdint.h>

#define N_NODES 50000
#define N_EDGES 600000
#define D 128
#define BM 128
#define BN 128
#define BK 16
#define NTILES 16                 // (2 halves) * (128 / BK)
#define M_PAD 50048               // N_NODES rounded up to multiple of BM

// ---------------- scratch (no allocations allowed) ----------------
__device__ int   g_count[N_NODES];
__device__ int   g_rowptr[N_NODES + 1];
__device__ int   g_cursor[N_NODES];
__device__ int   g_esrc[N_EDGES];
__device__ float g_deginv[N_NODES];
__device__ float g_hn[M_PAD * D];   // aggregated neighbor features (padded)
__device__ float g_hA[M_PAD * D];   // layer-1 output (padded)
__device__ float g_hB[M_PAD * D];   // layer-2 output (padded)

// ---------------- packed f32x2 FMA (Blackwell) ----------------
__device__ __forceinline__ float2 ffma2(float2 a, float2 b, float2 c) {
    union U { float2 f; unsigned long long u; };
    U ua, ub, uc, ud;
    ua.f = a; ub.f = b; uc.f = c;
    asm("fma.rn.f32x2 %0, %1, %2, %3;" : "=l"(ud.u) : "l"(ua.u), "l"(ub.u), "l"(uc.u));
    return ud.f;
}

// ---------------- CSR build ----------------
__global__ void k_zero_counts() {
    int i = blockIdx.x * blockDim.x + threadIdx.x;
    if (i < N_NODES) g_count[i] = 0;
}

__global__ void k_hist(const int* __restrict__ dst) {
    int e = blockIdx.x * blockDim.x + threadIdx.x;
    if (e < N_EDGES) atomicAdd(&g_count[dst[e]], 1);
}

// single-block exclusive scan over 50000 counts; also fills cursor + deg_inv
__global__ void k_scan() {
    __shared__ int sums[1024];
    const int CH = (N_NODES + 1023) / 1024;  // 49
    int t = threadIdx.x;
    int beg = t * CH;
    int end = min(beg + CH, N_NODES);
    int s = 0;
    for (int i = beg; i < end; i++) s += g_count[i];
    sums[t] = s;
    __syncthreads();
    // Hillis-Steele inclusive scan
    for (int off = 1; off < 1024; off <<= 1) {
        int v = (t >= off) ? sums[t - off] : 0;
        __syncthreads();
        sums[t] += v;
        __syncthreads();
    }
    int run = (t == 0) ? 0 : sums[t - 1];  // exclusive prefix for this chunk
    for (int i = beg; i < end; i++) {
        g_rowptr[i] = run;
        g_cursor[i] = run;
        int c = g_count[i];
        g_deginv[i] = 1.0f / fmaxf((float)c, 1.0f);
        run += c;
    }
    if (t == 1023) g_rowptr[N_NODES] = run;
}

__global__ void k_scatter(const int* __restrict__ src, const int* __restrict__ dst) {
    int e = blockIdx.x * blockDim.x + threadIdx.x;
    if (e < N_EDGES) {
        int p = atomicAdd(&g_cursor[dst[e]], 1);
        g_esrc[p] = src[e];
    }
}

// ---------------- neighbor aggregation: one warp per node ----------------
__global__ void k_agg(const float* __restrict__ h, float* __restrict__ out) {
    int node = (blockIdx.x * blockDim.x + threadIdx.x) >> 5;
    int lane = threadIdx.x & 31;
    if (node >= N_NODES) return;
    int beg = g_rowptr[node];
    int end = g_rowptr[node + 1];
    float4 acc0 = make_float4(0.f, 0.f, 0.f, 0.f);
    float4 acc1 = make_float4(0.f, 0.f, 0.f, 0.f);
    int e = beg;
    for (; e + 1 < end; e += 2) {
        int s0 = g_esrc[e];
        int s1 = g_esrc[e + 1];
        float4 v0 = ((const float4*)(h + (size_t)s0 * D))[lane];
        float4 v1 = ((const float4*)(h + (size_t)s1 * D))[lane];
        acc0.x += v0.x; acc0.y += v0.y; acc0.z += v0.z; acc0.w += v0.w;
        acc1.x += v1.x; acc1.y += v1.y; acc1.z += v1.z; acc1.w += v1.w;
    }
    if (e < end) {
        int s0 = g_esrc[e];
        float4 v0 = ((const float4*)(h + (size_t)s0 * D))[lane];
        acc0.x += v0.x; acc0.y += v0.y; acc0.z += v0.z; acc0.w += v0.w;
    }
    float di = g_deginv[node];
    float4 r;
    r.x = (acc0.x + acc1.x) * di;
    r.y = (acc0.y + acc1.y) * di;
    r.z = (acc0.z + acc1.z) * di;
    r.w = (acc0.w + acc1.w) * di;
    ((float4*)(out + (size_t)node * D))[lane] = r;
}

// ---------------- fused dual GEMM: out = A0*W0 + A1*W1 + b, optional relu ----
// BM=128, BN=128(full), BK=16, 256 threads, 8x8 micro-tile via f32x2.
// Double-buffered smem: one __syncthreads per k-tile.
// guardA: A0 has exactly M valid rows (layer 1's g_features); scratch A's are padded.
__global__ __launch_bounds__(256) void k_gemm(
    const float* __restrict__ A0, const float* __restrict__ A1,
    const float* __restrict__ W0, const float* __restrict__ W1,
    const float* __restrict__ bias, float* __restrict__ out,
    int M, int relu, int guardA, int guardOut)
{
    __shared__ float As[2][BK][BM + 4];
    __shared__ float Bs[2][BK][BN];

    int tid = threadIdx.x;
    int tx = tid & 15;        // output col group: cols tx*8 .. tx*8+7
    int ty = tid >> 4;        // output row group: rows ty*8 .. ty*8+7
    int rowBase = blockIdx.x * BM;

    float2 acc[8][4];
#pragma unroll
    for (int r = 0; r < 8; r++)
#pragma unroll
        for (int c = 0; c < 4; c++) acc[r][c] = make_float2(0.f, 0.f);

    // per-thread load coordinates (each thread moves 2 float4 for A, 2 for B)
    int a_r0  = tid >> 2;                 // rows 0..63
    int a_r1  = a_r0 + 64;                // rows 64..127
    int a_c4  = tid & 3;                  // which float4 of the 16 k-cols
    int b_kr0 = tid >> 5;                 // k-rows 0..7
    int b_kr1 = b_kr0 + 8;                // k-rows 8..15
    int b_c4  = tid & 31;                 // 32 float4 per 128-col row

    // tile t: t<8 -> (A0,W0) k0=t*16 ; t>=8 -> (A1,W1) k0=(t-8)*16
    auto load_tile = [&](int t, int buf) {
        const float* A = (t < 8) ? A0 : A1;
        const float* W = (t < 8) ? W0 : W1;
        int grd = (t < 8) ? guardA : 0;    // A1 (g_hn) is always padded
        int k0 = (t & 7) * BK;
        // A tile: 128 rows x 16 k, transposed into As[buf][k][row]
        {
            int row = rowBase + a_r0;
            float4 v = make_float4(0.f, 0.f, 0.f, 0.f);
            if (!grd || row < M) v = *(const float4*)(A + (size_t)row * D + k0 + a_c4 * 4);
            As[buf][a_c4 * 4 + 0][a_r0] = v.x;
            As[buf][a_c4 * 4 + 1][a_r0] = v.y;
            As[buf][a_c4 * 4 + 2][a_r0] = v.z;
            As[buf][a_c4 * 4 + 3][a_r0] = v.w;
        }
        {
            int row = rowBase + a_r1;
            float4 v = make_float4(0.f, 0.f, 0.f, 0.f);
            if (!grd || row < M) v = *(const float4*)(A + (size_t)row * D + k0 + a_c4 * 4);
            As[buf][a_c4 * 4 + 0][a_r1] = v.x;
            As[buf][a_c4 * 4 + 1][a_r1] = v.y;
            As[buf][a_c4 * 4 + 2][a_r1] = v.z;
            As[buf][a_c4 * 4 + 3][a_r1] = v.w;
        }
        // W tile: 16 k-rows x 128 cols
        *(float4*)&Bs[buf][b_kr0][b_c4 * 4] =
            *(const float4*)(W + (size_t)(k0 + b_kr0) * D + b_c4 * 4);
        *(float4*)&Bs[buf][b_kr1][b_c4 * 4] =
            *(const float4*)(W + (size_t)(k0 + b_kr1) * D + b_c4 * 4);
    };

    load_tile(0, 0);
    __syncthreads();

#pragma unroll 1
    for (int t = 0; t < NTILES; t++) {
        int cur = t & 1;
        if (t + 1 < NTILES) load_tile(t + 1, 1 - cur);   // fill other buffer

#pragma unroll
        for (int k = 0; k < BK; k++) {
            float4 a0 = *(float4*)&As[cur][k][ty * 8];
            float4 a1 = *(float4*)&As[cur][k][ty * 8 + 4];
            float4 b0 = *(float4*)&Bs[cur][k][tx * 8];
            float4 b1 = *(float4*)&Bs[cur][k][tx * 8 + 4];
            float a[8] = {a0.x, a0.y, a0.z, a0.w, a1.x, a1.y, a1.z, a1.w};
            float2 bp[4] = {make_float2(b0.x, b0.y), make_float2(b0.z, b0.w),
                            make_float2(b1.x, b1.y), make_float2(b1.z, b1.w)};
#pragma unroll
            for (int r = 0; r < 8; r++) {
                float2 ar = make_float2(a[r], a[r]);
#pragma unroll
                for (int c = 0; c < 4; c++)
                    acc[r][c] = ffma2(ar, bp[c], acc[r][c]);
            }
        }
        // one barrier per tile: protects next iter's compute (buf 1-cur) and
        // the overwrite of buf cur at iter t+1's load
        __syncthreads();
    }

    // epilogue: + bias, optional relu, store
    float4 bi0 = *(const float4*)(bias + tx * 8);
    float4 bi1 = *(const float4*)(bias + tx * 8 + 4);
    float bb[8] = {bi0.x, bi0.y, bi0.z, bi0.w, bi1.x, bi1.y, bi1.z, bi1.w};
#pragma unroll
    for (int r = 0; r < 8; r++) {
        int row = rowBase + ty * 8 + r;
        if (guardOut && row >= M) continue;
        float o[8];
        o[0] = acc[r][0].x + bb[0]; o[1] = acc[r][0].y + bb[1];
        o[2] = acc[r][1].x + bb[2]; o[3] = acc[r][1].y + bb[3];
        o[4] = acc[r][2].x + bb[4]; o[5] = acc[r][2].y + bb[5];
        o[6] = acc[r][3].x + bb[6]; o[7] = acc[r][3].y + bb[7];
        if (relu) {
#pragma unroll
            for (int j = 0; j < 8; j++) o[j] = fmaxf(o[j], 0.f);
        }
        float* p = out + (size_t)row * D + tx * 8;
        *(float4*)(p)     = make_float4(o[0], o[1], o[2], o[3]);
        *(float4*)(p + 4) = make_float4(o[4], o[5], o[6], o[7]);
    }
}

// ---------------- launch ----------------
extern "C" void kernel_launch(void* const* d_in, const int* in_sizes, int n_in,
                              void* d_out, int out_size) {
    const float* g_features = (const float*)d_in[0];
    const int*   src        = (const int*)d_in[1];
    const int*   dst        = (const int*)d_in[2];
    const float* W_self1    = (const float*)d_in[3];
    const float* W_neigh1   = (const float*)d_in[4];
    const float* b1         = (const float*)d_in[5];
    const float* W_self2    = (const float*)d_in[6];
    const float* W_neigh2   = (const float*)d_in[7];
    const float* b2         = (const float*)d_in[8];
    const float* W_self3    = (const float*)d_in[9];
    const float* W_neigh3   = (const float*)d_in[10];
    const float* b3         = (const float*)d_in[11];
    float* out = (float*)d_out;

    float *hn, *hA, *hB;
    cudaGetSymbolAddress((void**)&hn, g_hn);
    cudaGetSymbolAddress((void**)&hA, g_hA);
    cudaGetSymbolAddress((void**)&hB, g_hB);

    const int TB = 256;
    int nodeBlocks = (N_NODES + TB - 1) / TB;
    int edgeBlocks = (N_EDGES + TB - 1) / TB;
    int aggBlocks  = (N_NODES * 32 + TB - 1) / TB;   // warp per node
    int gemmBlocks = M_PAD / BM;                     // 391, exact

    // CSR build (once; reused by all 3 layers)
    k_zero_counts<<<nodeBlocks, TB>>>();
    k_hist<<<edgeBlocks, TB>>>(dst);
    k_scan<<<1, 1024>>>();
    k_scatter<<<edgeBlocks, TB>>>(src, dst);

    // layer 1 (A0 = harness input: guard A loads; out = padded scratch: no store guard)
    k_agg<<<aggBlocks, TB>>>(g_features, hn);
    k_gemm<<<gemmBlocks, 256>>>(g_features, hn, W_self1, W_neigh1, b1, hA,
                                N_NODES, 1, 1, 0);
    // layer 2 (all padded scratch: no guards)
    k_agg<<<aggBlocks, TB>>>(hA, hn);
    k_gemm<<<gemmBlocks, 256>>>(hA, hn, W_self2, W_neigh2, b2, hB,
                                N_NODES, 1, 0, 0);
    // layer 3 (out = harness d_out, exactly N_NODES rows: guard stores)
    k_agg<<<aggBlocks, TB>>>(hB, hn);
    k_gemm<<<gemmBlocks, 256>>>(hB, hn, W_self3, W_neigh3, b3, out,
                                N_NODES, 0, 0, 1);
}

// round 14
// speedup vs baseline: 1.4139x; 1.4139x over previous
#include <cuda_runtime.h>
#include <cuda_fp16.h>
#include <stdint.h>

#define N_NODES 50000
#define N_EDGES 600000
#define D 128
#define M_PAD 50048               // 391 * 128
#define N_TILES 391
#define GRID_GEMM 148
#define CNT_PAD 53248             // 1024 * 52

#define PITCH 136                 // halves per smem tile row (272B = 68 banks)
#define TILE_H (128 * PITCH)      // halves per tile (34816 B)

// ---------------- scratch (no allocations allowed) ----------------
__device__ __align__(16) int    g_count[CNT_PAD];
__device__ int    g_rowptr[N_NODES + 1];
__device__ int    g_cursor[N_NODES];
__device__ int    g_esrc[N_EDGES];
__device__ float  g_deginv[N_NODES];
__device__ __align__(16) float  g_hn[M_PAD * D];
__device__ __align__(16) float  g_hA[M_PAD * D];
__device__ __align__(16) float  g_hB[M_PAD * D];
__device__ __align__(16) __half g_whi[6 * D * D];   // Whi[n][k] (transposed, hi)
__device__ __align__(16) __half g_wlo[6 * D * D];   // Wlo[n][k] (transposed, lo)

// ================= CSR build =================
__global__ void k_zero_counts() {
    int i = blockIdx.x * blockDim.x + threadIdx.x;
    if (i < CNT_PAD) g_count[i] = 0;
}

__global__ void k_hist(const int* __restrict__ dst) {
    int e = blockIdx.x * blockDim.x + threadIdx.x;
    if (e < N_EDGES) atomicAdd(&g_count[dst[e]], 1);
}

__global__ void k_scan() {
    __shared__ int sums[1024];
    int t = threadIdx.x;
    const int4* cp = (const int4*)g_count;
    int base4 = t * 13;
    int s = 0;
#pragma unroll
    for (int i = 0; i < 13; i++) {
        int4 v = cp[base4 + i];
        s += v.x + v.y + v.z + v.w;
    }
    sums[t] = s;
    __syncthreads();
    for (int off = 1; off < 1024; off <<= 1) {
        int v = (t >= off) ? sums[t - off] : 0;
        __syncthreads();
        sums[t] += v;
        __syncthreads();
    }
    int run = (t == 0) ? 0 : sums[t - 1];
    int beg = t * 52;
#pragma unroll
    for (int i = 0; i < 13; i++) {
        int4 v = cp[base4 + i];
        int vals[4] = {v.x, v.y, v.z, v.w};
#pragma unroll
        for (int j = 0; j < 4; j++) {
            int idx = beg + i * 4 + j;
            if (idx < N_NODES) {
                g_rowptr[idx] = run;
                g_cursor[idx] = run;
                g_deginv[idx] = 1.0f / fmaxf((float)vals[j], 1.0f);
            }
            run += vals[j];
        }
    }
    if (t == 1023) g_rowptr[N_NODES] = run;
}

__global__ void k_scatter(const int* __restrict__ src, const int* __restrict__ dst) {
    int e = blockIdx.x * blockDim.x + threadIdx.x;
    if (e < N_EDGES) {
        int p = atomicAdd(&g_cursor[dst[e]], 1);
        g_esrc[p] = src[e];
    }
}

// ====== weight transpose + fp16 hi/lo split (6 matrices, one launch) ======
struct WtArgs { const float* w[6]; };

__global__ void k_wt(WtArgs args) {
    __shared__ float tile[32][33];
    const float* W = args.w[blockIdx.z];
    __half* Whi = g_whi + blockIdx.z * D * D;
    __half* Wlo = g_wlo + blockIdx.z * D * D;
    int bx = blockIdx.x * 32, by = blockIdx.y * 32;   // bx: n-range, by: k-range
#pragma unroll
    for (int j = 0; j < 32; j += 8)
        tile[threadIdx.y + j][threadIdx.x] = W[(by + threadIdx.y + j) * D + bx + threadIdx.x];
    __syncthreads();
#pragma unroll
    for (int j = 0; j < 32; j += 8) {
        float x = tile[threadIdx.x][threadIdx.y + j];   // W[k=by+tx][n=bx+ty+j]
        __half h = __float2half_rn(x);
        __half l = __float2half_rn(x - __half2float(h));
        int n = bx + threadIdx.y + j, k = by + threadIdx.x;
        Whi[n * D + k] = h;
        Wlo[n * D + k] = l;
    }
}

// ================= neighbor aggregation =================
__global__ void k_agg(const float* __restrict__ h, float* __restrict__ out) {
    int node = (blockIdx.x * blockDim.x + threadIdx.x) >> 5;
    int lane = threadIdx.x & 31;
    if (node >= N_NODES) return;
    int beg = g_rowptr[node];
    int end = g_rowptr[node + 1];
    float4 acc0 = make_float4(0.f, 0.f, 0.f, 0.f);
    float4 acc1 = make_float4(0.f, 0.f, 0.f, 0.f);
    int e = beg;
    for (; e + 1 < end; e += 2) {
        int s0 = g_esrc[e];
        int s1 = g_esrc[e + 1];
        float4 v0 = ((const float4*)(h + (size_t)s0 * D))[lane];
        float4 v1 = ((const float4*)(h + (size_t)s1 * D))[lane];
        acc0.x += v0.x; acc0.y += v0.y; acc0.z += v0.z; acc0.w += v0.w;
        acc1.x += v1.x; acc1.y += v1.y; acc1.z += v1.z; acc1.w += v1.w;
    }
    if (e < end) {
        int s0 = g_esrc[e];
        float4 v0 = ((const float4*)(h + (size_t)s0 * D))[lane];
        acc0.x += v0.x; acc0.y += v0.y; acc0.z += v0.z; acc0.w += v0.w;
    }
    float di = g_deginv[node];
    float4 r;
    r.x = (acc0.x + acc1.x) * di;
    r.y = (acc0.y + acc1.y) * di;
    r.z = (acc0.z + acc1.z) * di;
    r.w = (acc0.w + acc1.w) * di;
    ((float4*)(out + (size_t)node * D))[lane] = r;
}

// ================= HMMA split-fp16 dual GEMM (persistent) =================
// out = A0*W0 + A1*W1 + bias (+relu), each product via 3-term fp16 split:
//   A*W ~= Ahi*Whi + Alo*Whi + Ahi*Wlo   (lo*lo dropped, ~2^-22 relative)
// Smem (halves): [Ahi][Alo][W0hi][W0lo][W1hi][W1lo] each 128 x PITCH, + bias.
#define SM_AHI 0
#define SM_ALO (1 * TILE_H)
#define SM_W0H (2 * TILE_H)
#define SM_W0L (3 * TILE_H)
#define SM_W1H (4 * TILE_H)
#define SM_W1L (5 * TILE_H)
#define SM_BIAS_BYTES (6 * TILE_H * 2)
#define SMEM_BYTES (SM_BIAS_BYTES + 512 + 128)

__device__ __forceinline__ uint32_t pack2(__half a, __half b) {
    __half2 p = __halves2half2(a, b);
    return *(uint32_t*)&p;
}

// convert+split one 128x128 fp32 tile into Ahi/Alo smem (pitched)
__device__ __forceinline__ void fill_A(const float* __restrict__ src, int rowBase,
                                       __half* Ahi, __half* Alo, int tid, int guard) {
    for (int i = tid; i < 4096; i += 256) {
        int r = i >> 5;               // 0..127
        int c4 = (i & 31) << 2;       // 0..124 step 4
        int row = rowBase + r;
        float4 v = make_float4(0.f, 0.f, 0.f, 0.f);
        if (!guard || row < N_NODES)
            v = *(const float4*)(src + (size_t)row * D + c4);
        __half h0 = __float2half_rn(v.x), h1 = __float2half_rn(v.y);
        __half h2 = __float2half_rn(v.z), h3 = __float2half_rn(v.w);
        __half l0 = __float2half_rn(v.x - __half2float(h0));
        __half l1 = __float2half_rn(v.y - __half2float(h1));
        __half l2 = __float2half_rn(v.z - __half2float(h2));
        __half l3 = __float2half_rn(v.w - __half2float(h3));
        uint2 uh; uh.x = pack2(h0, h1); uh.y = pack2(h2, h3);
        uint2 ul; ul.x = pack2(l0, l1); ul.y = pack2(l2, l3);
        *(uint2*)&Ahi[r * PITCH + c4] = uh;
        *(uint2*)&Alo[r * PITCH + c4] = ul;
    }
}

// stage a 128x128 fp16 weight (row-major [n][k]) into pitched smem
__device__ __forceinline__ void fill_W(const __half* __restrict__ src, __half* dst,
                                       int tid) {
    for (int i = tid; i < 2048; i += 256) {       // 2048 x 8-half vectors
        int n = i >> 4;
        int k = (i & 15) << 3;
        uint4 v = *(const uint4*)(src + n * D + k);
        *(uint4*)&dst[n * PITCH + k] = v;
    }
}

// one K=128 MMA pass: acc += At(128x128) * Wt(128x128)^T-frag layout
__device__ __forceinline__ void mma_pass(const __half* At, const __half* Wt,
                                         float acc[2][8][4], int mbase, int nbase,
                                         int g, int q) {
#pragma unroll
    for (int k0 = 0; k0 < 128; k0 += 16) {
        uint32_t a[2][4];
#pragma unroll
        for (int mf = 0; mf < 2; mf++) {
            const __half* ar = At + (mbase + mf * 16 + g) * PITCH + k0 + q * 2;
            a[mf][0] = *(const uint32_t*)(ar);                 // row,   k lo
            a[mf][1] = *(const uint32_t*)(ar + 8 * PITCH);     // row+8, k lo
            a[mf][2] = *(const uint32_t*)(ar + 8);             // row,   k hi
            a[mf][3] = *(const uint32_t*)(ar + 8 * PITCH + 8); // row+8, k hi
        }
#pragma unroll
        for (int nf = 0; nf < 8; nf++) {
            const __half* br = Wt + (nbase + nf * 8 + g) * PITCH + k0 + q * 2;
            uint32_t b0 = *(const uint32_t*)(br);
            uint32_t b1 = *(const uint32_t*)(br + 8);
#pragma unroll
            for (int mf = 0; mf < 2; mf++) {
                asm volatile(
                    "mma.sync.aligned.m16n8k16.row.col.f32.f16.f16.f32 "
                    "{%0,%1,%2,%3}, {%4,%5,%6,%7}, {%8,%9}, {%0,%1,%2,%3};"
                    : "+f"(acc[mf][nf][0]), "+f"(acc[mf][nf][1]),
                      "+f"(acc[mf][nf][2]), "+f"(acc[mf][nf][3])
                    : "r"(a[mf][0]), "r"(a[mf][1]), "r"(a[mf][2]), "r"(a[mf][3]),
                      "r"(b0), "r"(b1));
            }
        }
    }
}

__global__ __launch_bounds__(256, 1) void k_gemm_mma(
    const float* __restrict__ A0, const float* __restrict__ A1,
    const __half* __restrict__ W0hi, const __half* __restrict__ W0lo,
    const __half* __restrict__ W1hi, const __half* __restrict__ W1lo,
    const float* __restrict__ bias, float* __restrict__ out,
    int relu, int guardA, int guardOut)
{
    extern __shared__ __half sm[];
    __half* Ahi = sm + SM_AHI;
    __half* Alo = sm + SM_ALO;
    __half* W0h = sm + SM_W0H;
    __half* W0l = sm + SM_W0L;
    __half* W1h = sm + SM_W1H;
    __half* W1l = sm + SM_W1L;
    float* bS = (float*)((char*)sm + SM_BIAS_BYTES);

    int tid = threadIdx.x;
    int wid = tid >> 5;
    int lane = tid & 31;
    int g = lane >> 2;        // groupID 0..7
    int q = lane & 3;         // quad 0..3
    int mbase = (wid & 3) * 32;
    int nbase = (wid >> 2) * 64;

    // stage resident weights + bias
    fill_W(W0hi, W0h, tid);
    fill_W(W0lo, W0l, tid);
    fill_W(W1hi, W1h, tid);
    fill_W(W1lo, W1l, tid);
    if (tid < D) bS[tid] = bias[tid];

    float acc[2][8][4];
#pragma unroll
    for (int mf = 0; mf < 2; mf++)
#pragma unroll
        for (int nf = 0; nf < 8; nf++)
#pragma unroll
            for (int c = 0; c < 4; c++) acc[mf][nf][c] = 0.f;

    for (int t = blockIdx.x; t < N_TILES; t += GRID_GEMM) {
        int rowBase = t * 128;

        __syncthreads();                       // A bufs free (prev readers done)
        fill_A(A0, rowBase, Ahi, Alo, tid, guardA);
        __syncthreads();
        mma_pass(Ahi, W0h, acc, mbase, nbase, g, q);
        mma_pass(Alo, W0h, acc, mbase, nbase, g, q);
        mma_pass(Ahi, W0l, acc, mbase, nbase, g, q);

        __syncthreads();                       // done reading A (self)
        fill_A(A1, rowBase, Ahi, Alo, tid, 0); // scratch A1 is padded
        __syncthreads();
        mma_pass(Ahi, W1h, acc, mbase, nbase, g, q);
        mma_pass(Alo, W1h, acc, mbase, nbase, g, q);
        mma_pass(Ahi, W1l, acc, mbase, nbase, g, q);

        // epilogue: bias, relu, store, zero acc
#pragma unroll
        for (int mf = 0; mf < 2; mf++) {
#pragma unroll
            for (int nf = 0; nf < 8; nf++) {
                int col = nbase + nf * 8 + q * 2;
                float b0 = bS[col], b1 = bS[col + 1];
                float o0 = acc[mf][nf][0] + b0;
                float o1 = acc[mf][nf][1] + b1;
                float o2 = acc[mf][nf][2] + b0;
                float o3 = acc[mf][nf][3] + b1;
                if (relu) {
                    o0 = fmaxf(o0, 0.f); o1 = fmaxf(o1, 0.f);
                    o2 = fmaxf(o2, 0.f); o3 = fmaxf(o3, 0.f);
                }
                int r0 = rowBase + mbase + mf * 16 + g;
                int r1 = r0 + 8;
                if (!guardOut || r0 < N_NODES)
                    *(float2*)(out + (size_t)r0 * D + col) = make_float2(o0, o1);
                if (!guardOut || r1 < N_NODES)
                    *(float2*)(out + (size_t)r1 * D + col) = make_float2(o2, o3);
                acc[mf][nf][0] = 0.f; acc[mf][nf][1] = 0.f;
                acc[mf][nf][2] = 0.f; acc[mf][nf][3] = 0.f;
            }
        }
    }
}

// ================= launch =================
extern "C" void kernel_launch(void* const* d_in, const int* in_sizes, int n_in,
                              void* d_out, int out_size) {
    const float* g_features = (const float*)d_in[0];
    const int*   src        = (const int*)d_in[1];
    const int*   dst        = (const int*)d_in[2];
    const float* W_self1    = (const float*)d_in[3];
    const float* W_neigh1   = (const float*)d_in[4];
    const float* b1         = (const float*)d_in[5];
    const float* W_self2    = (const float*)d_in[6];
    const float* W_neigh2   = (const float*)d_in[7];
    const float* b2         = (const float*)d_in[8];
    const float* W_self3    = (const float*)d_in[9];
    const float* W_neigh3   = (const float*)d_in[10];
    const float* b3         = (const float*)d_in[11];
    float* out = (float*)d_out;

    float *hn, *hA, *hB;
    __half *whi, *wlo;
    cudaGetSymbolAddress((void**)&hn, g_hn);
    cudaGetSymbolAddress((void**)&hA, g_hA);
    cudaGetSymbolAddress((void**)&hB, g_hB);
    cudaGetSymbolAddress((void**)&whi, g_whi);
    cudaGetSymbolAddress((void**)&wlo, g_wlo);

    cudaFuncSetAttribute(k_gemm_mma, cudaFuncAttributeMaxDynamicSharedMemorySize,
                         SMEM_BYTES);

    const int TB = 256;
    int cntBlocks  = (CNT_PAD + TB - 1) / TB;
    int edgeBlocks = (N_EDGES + TB - 1) / TB;
    int aggBlocks  = (N_NODES * 32 + TB - 1) / TB;

    // CSR build (reused by all 3 layers)
    k_zero_counts<<<cntBlocks, TB>>>();
    k_hist<<<edgeBlocks, TB>>>(dst);
    k_scan<<<1, 1024>>>();
    k_scatter<<<edgeBlocks, TB>>>(src, dst);

    // transpose + split all 6 weight matrices
    WtArgs wa;
    wa.w[0] = W_self1; wa.w[1] = W_neigh1;
    wa.w[2] = W_self2; wa.w[3] = W_neigh2;
    wa.w[4] = W_self3; wa.w[5] = W_neigh3;
    k_wt<<<dim3(4, 4, 6), dim3(32, 8)>>>(wa);

    // layer 1 (A0 = harness input: guard loads; out = padded scratch)
    k_agg<<<aggBlocks, TB>>>(g_features, hn);
    k_gemm_mma<<<GRID_GEMM, 256, SMEM_BYTES>>>(
        g_features, hn, whi + 0 * D * D, wlo + 0 * D * D,
        whi + 1 * D * D, wlo + 1 * D * D, b1, hA, 1, 1, 0);
    // layer 2
    k_agg<<<aggBlocks, TB>>>(hA, hn);
    k_gemm_mma<<<GRID_GEMM, 256, SMEM_BYTES>>>(
        hA, hn, whi + 2 * D * D, wlo + 2 * D * D,
        whi + 3 * D * D, wlo + 3 * D * D, b2, hB, 1, 0, 0);
    // layer 3 (out = d_out: guard stores)
    k_agg<<<aggBlocks, TB>>>(hB, hn);
    k_gemm_mma<<<GRID_GEMM, 256, SMEM_BYTES>>>(
        hB, hn, whi + 4 * D * D, wlo + 4 * D * D,
        whi + 5 * D * D, wlo + 5 * D * D, b3, out, 0, 0, 1);
}